// round 14
// baseline (speedup 1.0000x reference)
#include <cuda_runtime.h>
#include <cuda_bf16.h>
#include <cstdint>

#define NN 100000
#define EE 600000
#define NB_CHUNK 98  // ceil(NN/1024)

// ---- scratch (device globals; allocation is forbidden) ----
__device__ int   g_deg[NN];
__device__ int   g_off[NN];
__device__ int   g_cursor[NN];
__device__ float g_invdeg[NN];
__device__ int   g_csrc[EE];
__device__ volatile int g_blkTotal[NB_CHUNK];
__device__ volatile int g_blkFlag[NB_CHUNK];
__device__ float g_xr[(size_t)NN * 128];   // tf32-rounded x
__device__ float g_agg[(size_t)NN * 128];  // tf32-rounded mean_nbr(xr)
__device__ float g_Q[(size_t)NN * 64];     // [h@W2l | h@W2r]
__device__ float g_Wr[32768];              // rounded [W1l | W1r], each [128k][128n]
__device__ float g_W2[8192];               // rounded [W2l | W2r] as [128k][64n]
__device__ int   g_is64;

__device__ __forceinline__ unsigned f2tf(float f) {
    unsigned r;
    asm("cvt.rna.tf32.f32 %0, %1;" : "=r"(r) : "f"(f));
    return r;
}
__device__ __forceinline__ float f2tff(float f) {
    return __uint_as_float(f2tf(f));
}

// ---------------- init: zero deg/flags, detect edge dtype, round weights ----
__global__ void k_init(const void* ei, const float* W1l, const float* W1r,
                       const float* W2l, const float* W2r) {
    int i = blockIdx.x * blockDim.x + threadIdx.x;
    if (i < NN) g_deg[i] = 0;
    if (i < NB_CHUNK) g_blkFlag[i] = 0;
    if (i < 16384) {
        g_Wr[i] = f2tff(W1l[i]);          // [k][n] row-major, as stored
        g_Wr[i + 16384] = f2tff(W1r[i]);
    } else if (i < 24576) {
        int j = i - 16384;                 // j = k*64 + n
        int k = j >> 6, n = j & 63;
        g_W2[j] = f2tff(n < 32 ? W2l[k * 32 + n] : W2r[k * 32 + n - 32]);
    }
    if (i == 0) {
        const long long* p = (const long long*)ei;
        int ok = 1;
        for (int k = 0; k < 32; k++) {
            long long v = p[k];
            if (v < 0 || v >= NN) ok = 0;
        }
        g_is64 = ok;
    }
}

// ---------------- count + x-round fused (both lightweight roles) ----------
#define XB 6400  // x-round blocks: 6400*512 float4 slots >= 3.2M
__global__ __launch_bounds__(256) void k_count_round(const void* ei, const float* x) {
    int b = blockIdx.x, t = threadIdx.x;
    if (b < XB) {
        const float4* src = (const float4*)x;
        float4* dst = (float4*)g_xr;
#pragma unroll
        for (int j = 0; j < 2; j++) {
            int pos = b * 512 + j * 256 + t;
            if (pos < NN * 32) {
                float4 v = src[pos];
                v.x = f2tff(v.x); v.y = f2tff(v.y);
                v.z = f2tff(v.z); v.w = f2tff(v.w);
                dst[pos] = v;
            }
        }
        return;
    }
    int e = (b - XB) * 256 + t;
    if (e >= EE / 2) return;
    int d0, d1;
    if (g_is64) {
        longlong2 v = ((const longlong2*)ei)[EE / 2 + e];
        d0 = (int)v.x; d1 = (int)v.y;
    } else {
        int2 v = ((const int2*)ei)[EE / 2 + e];
        d0 = v.x; d1 = v.y;
    }
    atomicAdd(&g_deg[d0], 1);
    atomicAdd(&g_deg[d1], 1);
}

// Single-kernel exclusive scan of g_deg with parallel decoupled lookback.
__global__ __launch_bounds__(256) void k_scan() {
    __shared__ int tsum[256];
    __shared__ int tpre[256];
    __shared__ int red[256];
    __shared__ int sh_prefix;
    int b = blockIdx.x, t = threadIdx.x;
    int base = b * 1024;
    int v[4];
    int s = 0;
#pragma unroll
    for (int j = 0; j < 4; j++) {
        int i = base + t * 4 + j;
        v[j] = (i < NN) ? g_deg[i] : 0;
        s += v[j];
    }
    tsum[t] = s;
    __syncthreads();
    if (t == 0) {
        int acc = 0;
        for (int k = 0; k < 256; k++) {
            tpre[k] = acc;
            acc += tsum[k];
        }
        g_blkTotal[b] = acc;
        __threadfence();
        g_blkFlag[b] = 1;
    }
    int mine = 0;
    if (t < b) {
        while (g_blkFlag[t] == 0) {}
        mine = g_blkTotal[t];
    }
    red[t] = mine;
    __syncthreads();
    for (int o = 128; o > 0; o >>= 1) {
        if (t < o) red[t] += red[t + o];
        __syncthreads();
    }
    if (t == 0) sh_prefix = red[0];
    __syncthreads();
    int acc = sh_prefix + tpre[t];
#pragma unroll
    for (int j = 0; j < 4; j++) {
        int i = base + t * 4 + j;
        if (i < NN) {
            g_off[i] = acc;
            g_cursor[i] = acc;
            g_invdeg[i] = 1.0f / fmaxf((float)v[j], 1.0f);
        }
        acc += v[j];
    }
}

__global__ void k_fill(const void* ei) {
    int e = blockIdx.x * blockDim.x + threadIdx.x;
    if (e >= EE / 2) return;
    int s0, s1, d0, d1;
    if (g_is64) {
        longlong2 sv = ((const longlong2*)ei)[e];
        longlong2 dv = ((const longlong2*)ei)[EE / 2 + e];
        s0 = (int)sv.x; s1 = (int)sv.y; d0 = (int)dv.x; d1 = (int)dv.y;
    } else {
        int2 sv = ((const int2*)ei)[e];
        int2 dv = ((const int2*)ei)[EE / 2 + e];
        s0 = sv.x; s1 = sv.y; d0 = dv.x; d1 = dv.y;
    }
    g_csrc[atomicAdd(&g_cursor[d0], 1)] = s0;
    g_csrc[atomicAdd(&g_cursor[d1], 1)] = s1;
}

// ---------------- cp.async helpers ----------------
__device__ __forceinline__ void cp16(unsigned smem, const void* g, bool valid) {
    int sz = valid ? 16 : 0;  // sz<16 zero-fills
    asm volatile("cp.async.ca.shared.global [%0], [%1], 16, %2;\n"
                 :: "r"(smem), "l"(g), "r"(sz));
}
__device__ __forceinline__ void cp_commit() {
    asm volatile("cp.async.commit_group;\n" ::: "memory");
}
__device__ __forceinline__ void cp_wait0() {
    asm volatile("cp.async.wait_group 0;\n" ::: "memory");
}
__device__ __forceinline__ void cp_wait1() {
    asm volatile("cp.async.wait_group 1;\n" ::: "memory");
}

__device__ __forceinline__ void mma8(float* c, const unsigned* a, const unsigned* b) {
    asm volatile(
        "mma.sync.aligned.m16n8k8.row.col.f32.tf32.tf32.f32 "
        "{%0,%1,%2,%3},{%4,%5,%6,%7},{%8,%9},{%0,%1,%2,%3};"
        : "+f"(c[0]), "+f"(c[1]), "+f"(c[2]), "+f"(c[3])
        : "r"(a[0]), "r"(a[1]), "r"(a[2]), "r"(a[3]), "r"(b[0]), "r"(b[1]));
}

// ---------------- fused layer-1 + layer-2 GEMM ----------------
// Stage 1: h_tile = relu([agg | xr] @ [W1l; W1r] + b1), K=256, h kept in SMEM.
// Stage 2: Q_tile = h_tile @ W2c, K=128, W2c preloaded via first cp.async group.
__global__ __launch_bounds__(256, 2) void k_fused12(
    const float* __restrict__ A1, const float* __restrict__ A2,
    const float* __restrict__ B0, const float* __restrict__ B1,
    const float* __restrict__ W2c, const float* __restrict__ bias,
    float* __restrict__ Q) {
    constexpr int LDA = 36, LDB = 136;
    constexpr int ASZ = 128 * LDA;  // 4608
    constexpr int BSZ = 32 * LDB;   // 4352
    constexpr int HCH = 128 * 36;   // 4608
    constexpr int W2CH = 32 * 72;   // 2304

    extern __shared__ unsigned sh[];
    unsigned* As = sh;
    unsigned* Bs = sh + 2 * ASZ;
    unsigned* hS = sh;             // reused after stage-1 mainloop
    unsigned* W2s = sh + 18432;

    int t = threadIdx.x;
    int lane = t & 31, w = t >> 5;
    int gid = lane >> 2, tid4 = lane & 3;
    int rowBase = blockIdx.x * 128;

    unsigned shbase;
    asm("{ .reg .u64 tmp; cvta.to.shared.u64 tmp, %1; cvt.u32.u64 %0, tmp; }"
        : "=r"(shbase) : "l"((void*)sh));

    int wm = (w >> 2) * 64;   // stage-1: 2x4 warps, WM=64, WN=32
    int wn = (w & 3) * 32;

    auto issueTile = [&](int k0, int buf) {
        const float* Ap = (k0 < 128) ? A1 : A2;
        const float* Wp = (k0 < 128) ? B0 : B1;
        int ka = k0 & 127;
        unsigned Ab = shbase + (unsigned)(buf * ASZ) * 4u;
        unsigned Bb = shbase + (unsigned)(2 * ASZ + buf * BSZ) * 4u;
#pragma unroll
        for (int i = 0; i < 4; i++) {
            int idx = t + i * 256;
            int r = idx >> 3, seg = idx & 7;
            int grow = rowBase + r;
            cp16(Ab + (unsigned)(r * LDA + seg * 4) * 4u,
                 &Ap[(size_t)grow * 128 + ka + seg * 4], grow < NN);
        }
#pragma unroll
        for (int i = 0; i < 4; i++) {
            int idx = t + i * 256;
            int kk = idx >> 5;
            int n = (idx & 31) * 4;
            cp16(Bb + (unsigned)(kk * LDB + n) * 4u,
                 &Wp[(size_t)(ka + kk) * 128 + n], true);
        }
        if (k0 == 0) {  // W2 preload rides in the first commit group
#pragma unroll
            for (int i = 0; i < 8; i++) {
                int idx = t + i * 256;
                int ck = idx >> 9;
                int rem = idx & 511;
                int kk = rem >> 4;
                int n = (rem & 15) * 4;
                cp16(shbase + (unsigned)(18432 + ck * W2CH + kk * 72 + n) * 4u,
                     &W2c[(size_t)(ck * 32 + kk) * 64 + n], true);
            }
        }
        cp_commit();
    };

    float acc[4][4][4];
#pragma unroll
    for (int mi = 0; mi < 4; mi++)
#pragma unroll
        for (int ni = 0; ni < 4; ni++)
#pragma unroll
            for (int j = 0; j < 4; j++) acc[mi][ni][j] = 0.f;

    issueTile(0, 0);
    issueTile(32, 1);

#pragma unroll
    for (int c = 0; c < 8; c++) {
        int buf = c & 1;
        if (c + 1 < 8) cp_wait1(); else cp_wait0();
        __syncthreads();
        const unsigned* Ab = As + buf * ASZ;
        const unsigned* Bb = Bs + buf * BSZ;
#pragma unroll
        for (int ks = 0; ks < 32; ks += 8) {
            unsigned a[4][4], b[4][2];
#pragma unroll
            for (int mi = 0; mi < 4; mi++) {
                int r = wm + mi * 16 + gid;
                a[mi][0] = Ab[r * LDA + ks + tid4];
                a[mi][1] = Ab[(r + 8) * LDA + ks + tid4];
                a[mi][2] = Ab[r * LDA + ks + tid4 + 4];
                a[mi][3] = Ab[(r + 8) * LDA + ks + tid4 + 4];
            }
#pragma unroll
            for (int ni = 0; ni < 4; ni++) {
                int cc = wn + ni * 8 + gid;
                b[ni][0] = Bb[(ks + tid4) * LDB + cc];
                b[ni][1] = Bb[(ks + tid4 + 4) * LDB + cc];
            }
#pragma unroll
            for (int mi = 0; mi < 4; mi++)
#pragma unroll
                for (int ni = 0; ni < 4; ni++) mma8(acc[mi][ni], a[mi], b[ni]);
        }
        if (c + 2 < 8) {
            __syncthreads();            // all warps done reading buf
            issueTile((c + 2) * 32, buf);
        }
    }
    __syncthreads();  // everyone done with As/Bs before hS overwrite

    // stage-1 epilogue: h = rna(relu(acc + bias)) -> hS chunks
#pragma unroll
    for (int mi = 0; mi < 4; mi++) {
#pragma unroll
        for (int ni = 0; ni < 4; ni++) {
            int r0 = wm + mi * 16 + gid;
            int cc = wn + ni * 8 + 2 * tid4;
            float bx = bias[cc], by = bias[cc + 1];
            int ck = cc >> 5, kk = cc & 31;
            float2 v0, v1;
            v0.x = f2tff(fmaxf(acc[mi][ni][0] + bx, 0.f));
            v0.y = f2tff(fmaxf(acc[mi][ni][1] + by, 0.f));
            v1.x = f2tff(fmaxf(acc[mi][ni][2] + bx, 0.f));
            v1.y = f2tff(fmaxf(acc[mi][ni][3] + by, 0.f));
            *(float2*)&hS[ck * HCH + r0 * 36 + kk] = v0;
            *(float2*)&hS[ck * HCH + (r0 + 8) * 36 + kk] = v1;
        }
    }
    __syncthreads();

    // stage 2: Q = h @ W2c, 4x2 warps (WM=32, WN=32)
    int wm2 = (w >> 1) * 32;
    int wn2 = (w & 1) * 32;
    float acc2[2][4][4];
#pragma unroll
    for (int mi = 0; mi < 2; mi++)
#pragma unroll
        for (int ni = 0; ni < 4; ni++)
#pragma unroll
            for (int j = 0; j < 4; j++) acc2[mi][ni][j] = 0.f;

#pragma unroll
    for (int ck = 0; ck < 4; ck++) {
        const unsigned* Hc = hS + ck * HCH;
        const unsigned* Wc = W2s + ck * W2CH;
#pragma unroll
        for (int ks = 0; ks < 32; ks += 8) {
            unsigned a[2][4], b[4][2];
#pragma unroll
            for (int mi = 0; mi < 2; mi++) {
                int r = wm2 + mi * 16 + gid;
                a[mi][0] = Hc[r * 36 + ks + tid4];
                a[mi][1] = Hc[(r + 8) * 36 + ks + tid4];
                a[mi][2] = Hc[r * 36 + ks + tid4 + 4];
                a[mi][3] = Hc[(r + 8) * 36 + ks + tid4 + 4];
            }
#pragma unroll
            for (int ni = 0; ni < 4; ni++) {
                int cc = wn2 + ni * 8 + gid;
                b[ni][0] = Wc[(ks + tid4) * 72 + cc];
                b[ni][1] = Wc[(ks + tid4 + 4) * 72 + cc];
            }
#pragma unroll
            for (int mi = 0; mi < 2; mi++)
#pragma unroll
                for (int ni = 0; ni < 4; ni++) mma8(acc2[mi][ni], a[mi], b[ni]);
        }
    }

#pragma unroll
    for (int mi = 0; mi < 2; mi++) {
#pragma unroll
        for (int ni = 0; ni < 4; ni++) {
            int r0 = rowBase + wm2 + mi * 16 + gid;
            int cc = wn2 + ni * 8 + 2 * tid4;
            if (r0 < NN)
                *(float2*)&Q[(size_t)r0 * 64 + cc] =
                    make_float2(acc2[mi][ni][0], acc2[mi][ni][1]);
            if (r0 + 8 < NN)
                *(float2*)&Q[(size_t)(r0 + 8) * 64 + cc] =
                    make_float2(acc2[mi][ni][2], acc2[mi][ni][3]);
        }
    }
}

// ---------------- aggregations ----------------
__global__ void k_agg0(const float* __restrict__ feat, float* __restrict__ agg) {
    int node = (blockIdx.x * blockDim.x + threadIdx.x) >> 5;
    if (node >= NN) return;
    int lane = threadIdx.x & 31;
    int s = g_off[node], d = g_deg[node];
    const float4* F4 = (const float4*)feat;
    float4 acc = make_float4(0.f, 0.f, 0.f, 0.f);
    int k = 0;
    for (; k + 1 < d; k += 2) {
        int j0 = g_csrc[s + k], j1 = g_csrc[s + k + 1];
        float4 v0 = F4[(size_t)j0 * 32 + lane];
        float4 v1 = F4[(size_t)j1 * 32 + lane];
        acc.x += v0.x + v1.x; acc.y += v0.y + v1.y;
        acc.z += v0.z + v1.z; acc.w += v0.w + v1.w;
    }
    if (k < d) {
        int j = g_csrc[s + k];
        float4 v = F4[(size_t)j * 32 + lane];
        acc.x += v.x; acc.y += v.y; acc.z += v.z; acc.w += v.w;
    }
    float sc = g_invdeg[node];
    acc.x = f2tff(acc.x * sc); acc.y = f2tff(acc.y * sc);
    acc.z = f2tff(acc.z * sc); acc.w = f2tff(acc.w * sc);
    ((float4*)agg)[(size_t)node * 32 + lane] = acc;
}

__global__ void k_agg2(const float* __restrict__ Q, const float* __restrict__ b2,
                       float* __restrict__ out) {
    int node = (blockIdx.x * blockDim.x + threadIdx.x) >> 5;
    if (node >= NN) return;
    int lane = threadIdx.x & 31;
    int s = g_off[node], d = g_deg[node];
    float acc = 0.f;
    int k = 0;
    for (; k + 1 < d; k += 2) {
        int j0 = g_csrc[s + k], j1 = g_csrc[s + k + 1];
        acc += Q[(size_t)j0 * 64 + lane] + Q[(size_t)j1 * 64 + lane];
    }
    if (k < d) acc += Q[(size_t)g_csrc[s + k] * 64 + lane];
    out[(size_t)node * 32 + lane] =
        acc * g_invdeg[node] + b2[lane] + Q[(size_t)node * 64 + 32 + lane];
}

extern "C" void kernel_launch(void* const* d_in, const int* in_sizes, int n_in,
                              void* d_out, int out_size) {
    const float* x   = (const float*)d_in[0];
    const void*  ei  = d_in[1];
    const float* W1l = (const float*)d_in[2];
    const float* b1  = (const float*)d_in[3];
    const float* W1r = (const float*)d_in[4];
    const float* W2l = (const float*)d_in[5];
    const float* b2  = (const float*)d_in[6];
    const float* W2r = (const float*)d_in[7];
    float* out = (float*)d_out;

    float *xr = nullptr, *agg = nullptr, *Q = nullptr, *Wr = nullptr, *W2 = nullptr;
    cudaGetSymbolAddress((void**)&xr, g_xr);
    cudaGetSymbolAddress((void**)&agg, g_agg);
    cudaGetSymbolAddress((void**)&Q, g_Q);
    cudaGetSymbolAddress((void**)&Wr, g_Wr);
    cudaGetSymbolAddress((void**)&W2, g_W2);

    const int smemF = 27648 * (int)sizeof(unsigned);  // 110592 B
    cudaFuncSetAttribute(k_fused12,
                         cudaFuncAttributeMaxDynamicSharedMemorySize, smemF);

    const int CSRB = (EE / 2 + 255) / 256;
    const int AGGB = (NN + 7) / 8;
    const int MBLK = (NN + 127) / 128;

    k_init<<<(NN + 255) / 256, 256>>>(ei, W1l, W1r, W2l, W2r);
    k_count_round<<<XB + CSRB, 256>>>(ei, x);
    k_scan<<<NB_CHUNK, 256>>>();
    k_fill<<<CSRB, 256>>>(ei);

    k_agg0<<<AGGB, 256>>>(xr, agg);
    k_fused12<<<MBLK, 256, smemF>>>(agg, xr, Wr, Wr + 16384, W2, b1, Q);

    k_agg2<<<AGGB, 256>>>(Q, b2, out);
}